// round 8
// baseline (speedup 1.0000x reference)
#include <cuda_runtime.h>
#include <cstdint>
#include <cstddef>

#define NB 8
#define NN 10000
#define NE 320000
#define HH 128
#define FN 64
#define ED 16
#define MM 15
#define FMAX 2048
#define BCAP 96

typedef unsigned long long ull;

// ---------------- scratch (device globals; no allocation allowed) ----------------
__device__ int   g_cnt[NB * NN];
__device__ int   g_bcol[(size_t)NB * NN * BCAP];
__device__ int   g_beid[(size_t)NB * NN * BCAP];
__device__ float g_aggea[NB * NN * ED];
__device__ float g_H1[(size_t)NB * NN * HH];
__device__ float g_H2[(size_t)NB * NN * HH];
__device__ float g_H3[NB * MM * HH];
__device__ float g_pre[(size_t)NB * NN * 80];   // layer0: stride 80; layer1 reuses (NB*FMAX*144 < this)
__device__ float g_Wc0[80 * 128];               // [W_in@W_nb0[:128] ; W_nb0[128:144]]
__device__ float g_Wxs[64 * 128];               // W_in@W_self0
__device__ float g_bc[128];                     // b_nb0 + b_in@W_nb0[:128]
__device__ float g_bs[128];                     // b_self0 + b_in@W_self0
__device__ int   g_front[NB * FMAX];
__device__ int   g_fcnt[NB];

// ---------------- f32x2 helpers ----------------
__device__ __forceinline__ ull pk2(float lo, float hi) {
    ull r; asm("mov.b64 %0, {%1,%2};" : "=l"(r) : "f"(lo), "f"(hi)); return r;
}
__device__ __forceinline__ float2 upk2(ull v) {
    float2 f; asm("mov.b64 {%0,%1}, %2;" : "=f"(f.x), "=f"(f.y) : "l"(v)); return f;
}
__device__ __forceinline__ void fma2(ull& d, ull a, ull b) {
    asm("fma.rn.f32x2 %0, %1, %2, %0;" : "+l"(d) : "l"(a), "l"(b));
}

// ---------------- bucketed CSR: single scatter pass ----------------
__global__ void scatter_k(const int* __restrict__ ei) {
    int idx = blockIdx.x * blockDim.x + threadIdx.x;
    if (idx >= NB * NE) return;
    int b = idx / NE, e = idx - b * NE;
    int src = ei[(size_t)b * 2 * NE + e];
    int dst = ei[(size_t)b * 2 * NE + NE + e];
    int off = atomicAdd(&g_cnt[b * NN + dst], 1);
    if (off < BCAP) {
        size_t base = ((size_t)(b * NN + dst)) * BCAP + off;
        g_bcol[base] = src;
        g_beid[base] = e;
    }
}

// ---------------- composite weights for layer 0 (4 lanes per output + shfl) ----------------
// outputs o in [0,16384): mat = o>>13 (0 -> Wc0 x-part, 1 -> Wxs), k=(o>>7)&63, j=o&127
__global__ void compose_k(const float* __restrict__ Win, const float* __restrict__ bin,
                          const float* __restrict__ Wnb0, const float* __restrict__ bnb0,
                          const float* __restrict__ Wself0, const float* __restrict__ bself0) {
    if (blockIdx.x < 256) {
        int id = blockIdx.x * 256 + threadIdx.x;
        int o = id >> 2, p = id & 3;
        int mat = o >> 13;
        int k = (o >> 7) & 63, j = o & 127;
        const float* WB = mat ? Wself0 : Wnb0;
        const float* wr = Win + k * 128;
        float acc = 0.f;
        int m0 = p * 32;
#pragma unroll 8
        for (int m = m0; m < m0 + 32; m++)
            acc += __ldg(wr + m) * __ldg(WB + m * 128 + j);
        acc += __shfl_down_sync(0xffffffffu, acc, 2);
        acc += __shfl_down_sync(0xffffffffu, acc, 1);
        if (p == 0) {
            if (mat) g_Wxs[k * 128 + j] = acc;
            else     g_Wc0[k * 128 + j] = acc;
        }
    } else {
        int tid = threadIdx.x;
        if (tid < 256) {
            int j = tid & 127;
            const float* WB = (tid >> 7) ? Wself0 : Wnb0;
            float acc = 0.f;
#pragma unroll 8
            for (int m = 0; m < 128; m++)
                acc += __ldg(bin + m) * __ldg(WB + m * 128 + j);
            if (tid >> 7) g_bs[j] = acc + __ldg(bself0 + j);
            else          g_bc[j] = acc + __ldg(bnb0 + j);
        }
        for (int i = tid; i < ED * 128; i += 256)
            g_Wc0[FN * 128 + i] = __ldg(Wnb0 + 128 * 128 + i);
    }
}

// ---------------- layer-0 aggregation: warp per node; gathers x rows + ea rows ----------------
__global__ void aggx_k(const float* __restrict__ x, const float* __restrict__ ea) {
    int b = blockIdx.y;
    int n = blockIdx.x * (blockDim.x >> 5) + (threadIdx.x >> 5);
    if (n >= NN) return;
    int lane = threadIdx.x & 31;
    const float* xb = x + (size_t)b * NN * FN;
    const float* eab = ea + (size_t)b * NE * ED;
    float2 acc = __ldg((const float2*)(xb + (size_t)n * FN + lane * 2));  // self loop
    float ev = 0.f;
    int cnt = g_cnt[b * NN + n];
    if (cnt > BCAP) cnt = BCAP;
    size_t base = ((size_t)(b * NN + n)) * BCAP;
#pragma unroll 4
    for (int j = 0; j < cnt; j++) {
        int s = __ldg(&g_bcol[base + j]);
        int e = __ldg(&g_beid[base + j]);
        float2 v = __ldg((const float2*)(xb + (size_t)s * FN + lane * 2));
        acc.x += v.x; acc.y += v.y;
        if (lane < ED) ev += __ldg(eab + (size_t)e * ED + lane);
    }
    float inv = 1.0f / (float)(cnt + 1);
    float* pr = g_pre + ((size_t)b * NN + n) * 80;
    *(float2*)(pr + lane * 2) = make_float2(acc.x * inv, acc.y * inv);
    if (lane < ED) {
        pr[FN + lane] = ev * inv;
        g_aggea[(b * NN + n) * ED + lane] = ev;   // sum (reused by agg1/last)
    }
}

// ---------------- frontier (nodes needed from layer 1) ----------------
__global__ void frontier_k() {
    int b = blockIdx.x, tid = threadIdx.x;  // 256 threads
    __shared__ int offs[MM + 1];
    if (tid == 0) {
        int t = 0;
        for (int n = 0; n < MM; n++) {
            offs[n] = t;
            int c = g_cnt[b * NN + n];
            t += (c > BCAP) ? BCAP : c;
        }
        offs[MM] = t;
        g_fcnt[b] = MM + t;
    }
    __syncthreads();
    if (tid < MM) g_front[b * FMAX + tid] = tid;
    for (int idx = tid; idx < MM * BCAP; idx += 256) {
        int n = idx / BCAP, j = idx - n * BCAP;
        int c = g_cnt[b * NN + n];
        if (c > BCAP) c = BCAP;
        if (j < c)
            g_front[b * FMAX + MM + offs[n] + j] = g_bcol[((size_t)(b * NN + n)) * BCAP + j];
    }
}

// ---------------- layer-1 aggregation over frontier: warp per index ----------------
__global__ void agg1_k(const float* __restrict__ H) {
    int b = blockIdx.y;
    int i = blockIdx.x * (blockDim.x >> 5) + (threadIdx.x >> 5);
    if (i >= g_fcnt[b]) return;
    int n = g_front[b * FMAX + i];
    int lane = threadIdx.x & 31;
    const float* Hb = H + (size_t)b * NN * HH;
    float4 acc = __ldg((const float4*)(Hb + (size_t)n * HH + lane * 4));  // self
    int cnt = g_cnt[b * NN + n];
    if (cnt > BCAP) cnt = BCAP;
    size_t base = ((size_t)(b * NN + n)) * BCAP;
#pragma unroll 4
    for (int j = 0; j < cnt; j++) {
        int s = __ldg(&g_bcol[base + j]);
        float4 v = __ldg((const float4*)(Hb + (size_t)s * HH + lane * 4));
        acc.x += v.x; acc.y += v.y; acc.z += v.z; acc.w += v.w;
    }
    float inv = 1.0f / (float)(cnt + 1);
    float* pr = g_pre + ((size_t)b * FMAX + i) * 144;
    *(float4*)(pr + lane * 4) = make_float4(acc.x * inv, acc.y * inv, acc.z * inv, acc.w * inv);
    if (lane < 4) {
        float4 e4 = *(const float4*)(g_aggea + ((size_t)b * NN + n) * ED + lane * 4);
        *(float4*)(pr + HH + lane * 4) = make_float4(e4.x * inv, e4.y * inv, e4.z * inv, e4.w * inv);
    }
}

// ---------------- fused GEMM (+row-norm+relu); optional row indirection ----------------
// out[row] = A1[row]@W1 + A2[row]@W2 + b1 + b2. A1 stride K1, A2 stride K2.
// IDX: rows are compacted [0,fcnt); A1 indexed by compact row, A2/out by g_front.
template <int K1, int K2, bool NRM, bool IDX>
__global__ void __launch_bounds__(512) gemm_k(
    const float* __restrict__ A1, const float* __restrict__ A2,
    const float* __restrict__ W1, const float* __restrict__ W2,
    const float* __restrict__ b1, const float* __restrict__ b2,
    float* __restrict__ Hout)
{
    constexpr int KT = K1 + K2;
    constexpr int NSTG = KT / 16;
    extern __shared__ float sm[];
    float* Wc = sm;              // KT x 128
    float* As = sm + KT * 128;   // 16 x 128 (As[kk][row])
    int b = blockIdx.y;
    int nrows = IDX ? g_fcnt[b] : NN;
    int row0 = blockIdx.x * 128;
    if (row0 >= nrows) return;
    int tid = threadIdx.x;
    int tx = tid & 31, ty = tid >> 5;

    for (int i = tid; i < K1 * 128 / 4; i += 512) ((float4*)Wc)[i] = ((const float4*)W1)[i];
    for (int i = tid; i < K2 * 128 / 4; i += 512)
        ((float4*)(Wc + K1 * 128))[i] = ((const float4*)W2)[i];

    float4 bv = *(const float4*)(b1 + tx * 4);
    {
        float4 b2v = *(const float4*)(b2 + tx * 4);
        bv.x += b2v.x; bv.y += b2v.y; bv.z += b2v.z; bv.w += b2v.w;
    }
    ull acc[4][4];
#pragma unroll
    for (int rp = 0; rp < 4; rp++) {
        acc[rp][0] = pk2(bv.x, bv.x); acc[rp][1] = pk2(bv.y, bv.y);
        acc[rp][2] = pk2(bv.z, bv.z); acc[rp][3] = pk2(bv.w, bv.w);
    }
    int r = tid >> 2, cg = (tid & 3) * 4;
    int grow = row0 + r;
    bool valid = grow < nrows;
    int orow = grow;
    if (IDX && valid) orow = g_front[b * FMAX + grow];
    int rowb = ty * 8;

    for (int s = 0; s < NSTG; s++) {
        int k0 = s * 16;
        float4 av = make_float4(0.f, 0.f, 0.f, 0.f);
        if (valid) {
            if (k0 + cg < K1)
                av = *(const float4*)(A1 + ((size_t)b * (IDX ? FMAX : NN) + grow) * (size_t)K1 + k0 + cg);
            else
                av = *(const float4*)(A2 + ((size_t)b * NN + orow) * (size_t)K2 + (k0 - K1) + cg);
        }
        __syncthreads();
        As[(cg + 0) * 128 + r] = av.x;
        As[(cg + 1) * 128 + r] = av.y;
        As[(cg + 2) * 128 + r] = av.z;
        As[(cg + 3) * 128 + r] = av.w;
        __syncthreads();
#pragma unroll
        for (int kk = 0; kk < 16; kk++) {
            float4 wv = *(const float4*)(Wc + (size_t)(k0 + kk) * 128 + tx * 4);
            ull ww0 = pk2(wv.x, wv.x), ww1 = pk2(wv.y, wv.y);
            ull ww2 = pk2(wv.z, wv.z), ww3 = pk2(wv.w, wv.w);
#pragma unroll
            for (int rp = 0; rp < 4; rp++) {
                ull ap = *(const ull*)(As + kk * 128 + rowb + rp * 2);
                fma2(acc[rp][0], ap, ww0);
                fma2(acc[rp][1], ap, ww1);
                fma2(acc[rp][2], ap, ww2);
                fma2(acc[rp][3], ap, ww3);
            }
        }
    }

#pragma unroll
    for (int rp = 0; rp < 4; rp++) {
        float2 v0 = upk2(acc[rp][0]), v1 = upk2(acc[rp][1]);
        float2 v2 = upk2(acc[rp][2]), v3 = upk2(acc[rp][3]);
        int rA = row0 + rowb + rp * 2, rB = rA + 1;
        if (NRM) {
            float ssA = v0.x * v0.x + v1.x * v1.x + v2.x * v2.x + v3.x * v3.x;
            float ssB = v0.y * v0.y + v1.y * v1.y + v2.y * v2.y + v3.y * v3.y;
#pragma unroll
            for (int off = 16; off; off >>= 1) {
                ssA += __shfl_xor_sync(0xffffffffu, ssA, off);
                ssB += __shfl_xor_sync(0xffffffffu, ssB, off);
            }
            float sA = 1.0f / fmaxf(sqrtf(ssA), 1e-12f);
            float sB = 1.0f / fmaxf(sqrtf(ssB), 1e-12f);
            v0.x = fmaxf(v0.x * sA, 0.f); v1.x = fmaxf(v1.x * sA, 0.f);
            v2.x = fmaxf(v2.x * sA, 0.f); v3.x = fmaxf(v3.x * sA, 0.f);
            v0.y = fmaxf(v0.y * sB, 0.f); v1.y = fmaxf(v1.y * sB, 0.f);
            v2.y = fmaxf(v2.y * sB, 0.f); v3.y = fmaxf(v3.y * sB, 0.f);
        }
        if (rA < nrows) {
            int oA = IDX ? g_front[b * FMAX + rA] : rA;
            *(float4*)(Hout + ((size_t)b * NN + oA) * 128 + tx * 4) =
                make_float4(v0.x, v1.x, v2.x, v3.x);
        }
        if (rB < nrows) {
            int oB = IDX ? g_front[b * FMAX + rB] : rB;
            *(float4*)(Hout + ((size_t)b * NN + oB) * 128 + tx * 4) =
                make_float4(v0.y, v1.y, v2.y, v3.y);
        }
    }
}

// ---------------- layer 2 (l=2): only nodes 0..14 feed the head ----------------
__global__ void last_k(const float* __restrict__ Wnb, const float* __restrict__ Wself,
                       const float* __restrict__ bnb, const float* __restrict__ bself) {
    int b = blockIdx.y, n = blockIdx.x;  // n < MM
    int c = threadIdx.x;                 // 128 threads
    __shared__ float pre_s[144];
    __shared__ float h2_s[128];
    __shared__ float red[128];
    const float* Hb = g_H2 + (size_t)b * NN * HH;
    float self = Hb[(size_t)n * HH + c];
    h2_s[c] = self;
    int cnt = g_cnt[b * NN + n];
    if (cnt > BCAP) cnt = BCAP;
    size_t base = ((size_t)(b * NN + n)) * BCAP;
    float acc = self;
#pragma unroll 4
    for (int j = 0; j < cnt; j++) {
        int s = __ldg(&g_bcol[base + j]);
        acc += Hb[(size_t)s * HH + c];
    }
    float inv = 1.0f / (float)(cnt + 1);
    pre_s[c] = acc * inv;
    if (c < 16) pre_s[128 + c] = g_aggea[((size_t)b * NN + n) * ED + c] * inv;
    __syncthreads();
    float o = bnb[c] + bself[c];
#pragma unroll 4
    for (int k = 0; k < 144; k++) o += pre_s[k] * __ldg(Wnb + (size_t)k * 128 + c);
#pragma unroll 4
    for (int k = 0; k < 128; k++) o += h2_s[k] * __ldg(Wself + (size_t)k * 128 + c);
    red[c] = o * o;
    __syncthreads();
    for (int off = 64; off; off >>= 1) {
        if (c < off) red[c] += red[c + off];
        __syncthreads();
    }
    float nrm = sqrtf(red[0]);
    float v = fmaxf(o / fmaxf(nrm, 1e-12f), 0.f);
    g_H3[((size_t)b * MM + n) * HH + c] = v;
}

// ---------------- jump + score + actor head: one block per batch ----------------
__global__ void head_k(const float* __restrict__ Wj, const float* __restrict__ bj,
                       const float* __restrict__ Ws1, const float* __restrict__ bs1,
                       const float* __restrict__ Ws2, const float* __restrict__ bs2,
                       const float* __restrict__ Wa1, const float* __restrict__ ba1,
                       const float* __restrict__ Wa2, const float* __restrict__ ba2,
                       const int* __restrict__ aidx, float* __restrict__ out) {
    int b = blockIdx.x, t = threadIdx.x;  // 128 threads
    __shared__ float rwb[384];
    __shared__ float hjs[128];
    __shared__ float hid[64];
    __shared__ float sc[16];
    __shared__ float hid2[64];
    int ai = aidx[b];
    for (int r = 0; r < MM; r++) {
        rwb[t]       = g_H1[((size_t)b * NN + r) * HH + t];
        rwb[128 + t] = g_H2[((size_t)b * NN + r) * HH + t];
        rwb[256 + t] = g_H3[((size_t)b * MM + r) * HH + t];
        __syncthreads();
        float o = bj[t];
#pragma unroll 8
        for (int k = 0; k < 384; k++) o += rwb[k] * __ldg(Wj + (size_t)k * 128 + t);
        hjs[t] = o;
        __syncthreads();
        if (t < 64) {
            float a = bs1[t];
#pragma unroll 8
            for (int k = 0; k < 128; k++) a += hjs[k] * __ldg(Ws1 + k * 64 + t);
            hid[t] = fmaxf(a, 0.f);
        }
        __syncthreads();
        if (t == 0) {
            float ssum = bs2[0];
            for (int q = 0; q < 64; q++) ssum += hid[q] * __ldg(Ws2 + q);
            sc[r] = (r == ai) ? -10.0f : ssum;
        }
        __syncthreads();
    }
    if (t < 64) {
        float a = ba1[t];
        for (int r2 = 0; r2 < MM; r2++) a += sc[r2] * __ldg(Wa1 + r2 * 64 + t);
        hid2[t] = fmaxf(a, 0.f);
    }
    __syncthreads();
    if (t < MM) {
        float o = ba2[t];
        for (int q = 0; q < 64; q++) o += hid2[q] * __ldg(Wa2 + q * MM + t);
        out[b * MM + t] = o;
    }
}

// ---------------- host ----------------
extern "C" void kernel_launch(void* const* d_in, const int* in_sizes, int n_in,
                              void* d_out, int out_size) {
    const float* x      = (const float*)d_in[0];
    const int*   ei     = (const int*)d_in[1];
    const float* ea     = (const float*)d_in[2];
    const int*   aidx   = (const int*)d_in[3];
    const float* W_in   = (const float*)d_in[4];
    const float* b_in   = (const float*)d_in[5];
    const float* W_nb   = (const float*)d_in[6];
    const float* b_nb   = (const float*)d_in[7];
    const float* W_self = (const float*)d_in[8];
    const float* b_self = (const float*)d_in[9];
    const float* W_j    = (const float*)d_in[10];
    const float* b_j    = (const float*)d_in[11];
    const float* W_s1   = (const float*)d_in[12];
    const float* b_s1   = (const float*)d_in[13];
    const float* W_s2   = (const float*)d_in[14];
    const float* b_s2   = (const float*)d_in[15];
    const float* W_a1   = (const float*)d_in[16];
    const float* b_a1   = (const float*)d_in[17];
    const float* W_a2   = (const float*)d_in[18];
    const float* b_a2   = (const float*)d_in[19];
    float* out = (float*)d_out;

    void *p_cnt, *p_H1, *p_H2, *p_pre, *p_Wc0, *p_Wxs, *p_bc, *p_bs;
    cudaGetSymbolAddress(&p_cnt, g_cnt);
    cudaGetSymbolAddress(&p_H1, g_H1);
    cudaGetSymbolAddress(&p_H2, g_H2);
    cudaGetSymbolAddress(&p_pre, g_pre);
    cudaGetSymbolAddress(&p_Wc0, g_Wc0);
    cudaGetSymbolAddress(&p_Wxs, g_Wxs);
    cudaGetSymbolAddress(&p_bc, g_bc);
    cudaGetSymbolAddress(&p_bs, g_bs);

    const int smem_l0 = ((80 + 64) * 128 + 16 * 128) * 4;   // 81920
    const int smem_l1 = ((144 + 128) * 128 + 16 * 128) * 4; // 147456
    cudaFuncSetAttribute(gemm_k<80, 64, true, false>, cudaFuncAttributeMaxDynamicSharedMemorySize, smem_l0);
    cudaFuncSetAttribute(gemm_k<144, 128, true, true>, cudaFuncAttributeMaxDynamicSharedMemorySize, smem_l1);

    cudaMemsetAsync(p_cnt, 0, sizeof(int) * NB * NN);

    compose_k<<<257, 256>>>(W_in, b_in, W_nb, b_nb, W_self, b_self);

    int eb = (NB * NE + 255) / 256;
    scatter_k<<<eb, 256>>>(ei);

    dim3 ga((NN + 7) / 8, NB);
    aggx_k<<<ga, 256>>>(x, ea);

    dim3 gg((NN + 127) / 128, NB);
    gemm_k<80, 64, true, false><<<gg, 512, smem_l0>>>(
        (const float*)p_pre, x,
        (const float*)p_Wc0, (const float*)p_Wxs,
        (const float*)p_bc, (const float*)p_bs, (float*)p_H1);

    // layer 1 on frontier only
    frontier_k<<<NB, 256>>>();
    dim3 gf((FMAX + 7) / 8, NB);
    agg1_k<<<gf, 256>>>((const float*)p_H1);
    dim3 gg1(FMAX / 128, NB);
    gemm_k<144, 128, true, true><<<gg1, 512, smem_l1>>>(
        (const float*)p_pre, (const float*)p_H1,
        W_nb + 144 * 128, W_self + 128 * 128, b_nb + 128, b_self + 128,
        (float*)p_H2);

    // layer 2: only the MM nodes that feed the head
    last_k<<<dim3(MM, NB), 128>>>(W_nb + 2 * 144 * 128, W_self + 2 * 128 * 128,
                                  b_nb + 2 * 128, b_self + 2 * 128);

    head_k<<<NB, 128>>>(W_j, b_j, W_s1, b_s1, W_s2, b_s2,
                        W_a1, b_a1, W_a2, b_a2, aidx, out);
}